// round 7
// baseline (speedup 1.0000x reference)
#include <cuda_runtime.h>
#include <cuda_fp16.h>
#include <cstdint>

// Problem dims
#define BB 512
#define SS 512
#define II 256
#define HH 512
#define OO 256
#define G4 2048   // 4*HH, gate-interleaved: n = j*4 + gate, order (g,i,f,o)

#define PTHREADS 256
#define LTHREADS 512
#define NCTA2 128   // 32 nt x 4 group-pairs

#define LDA 520     // padded row stride (halfs) for smem tiles
#define LSTM_SMEM  (3 * 64 * LDA * 2)       // sW + sA_A + sA_B = 199,680 B
#define XPROJ_SMEM ((64 + 128) * 264 * 2)   // 101,376 B (2 CTAs/SM)

// ---------------- device-global scratch (no cudaMalloc; keep < ~1.5 GB) ----------------
__device__ __align__(16) __half g_W4x_h[(size_t)G4 * II];
__device__ __align__(16) __half g_W4h_h[(size_t)G4 * HH];
__device__ __align__(16) __half g_Wp_h[(size_t)OO * HH];
__device__ float  g_bias4[G4];
__device__ __align__(16) __half g_Xh[(size_t)BB * SS * II];  // x fp16 (128 MB)
__device__ __align__(16) __half g_XP[(size_t)SS * BB * G4];  // x-projections + bias (1 GB)
__device__ __align__(16) __half g_Hh[2][(size_t)BB * HH];
__device__ unsigned g_grp[8 * 32];   // per-group barrier counters, 128B apart
__device__ unsigned g_arrive;        // global barrier before projection

// ---------------- helpers ----------------
__device__ __forceinline__ float sigf(float x) {
    return __fdividef(1.f, 1.f + __expf(-x));
}
__device__ __forceinline__ float tanhfast(float x) {
    x = fminf(15.f, fmaxf(-15.f, x));
    float t = __expf(2.f * x);
    return __fdividef(t - 1.f, t + 1.f);
}
__device__ __forceinline__ void ldsm4(uint32_t* r, uint32_t addr) {
    asm volatile("ldmatrix.sync.aligned.m8n8.x4.shared.b16 {%0,%1,%2,%3}, [%4];"
                 : "=r"(r[0]), "=r"(r[1]), "=r"(r[2]), "=r"(r[3]) : "r"(addr));
}
__device__ __forceinline__ void mma16816(float* d, const uint32_t* a, const uint32_t* b) {
    asm volatile("mma.sync.aligned.m16n8k16.row.col.f32.f16.f16.f32 "
                 "{%0,%1,%2,%3},{%4,%5,%6,%7},{%8,%9},{%0,%1,%2,%3};"
                 : "+f"(d[0]), "+f"(d[1]), "+f"(d[2]), "+f"(d[3])
                 : "r"(a[0]), "r"(a[1]), "r"(a[2]), "r"(a[3]), "r"(b[0]), "r"(b[1]));
}
__device__ __forceinline__ void cpasync16(uint32_t dst, const void* src) {
    asm volatile("cp.async.cg.shared.global [%0], [%1], 16;" :: "r"(dst), "l"(src));
}
__device__ __forceinline__ void cpasync_commit() {
    asm volatile("cp.async.commit_group;" ::: "memory");
}
template <int N>
__device__ __forceinline__ void cpasync_waitg() {
    asm volatile("cp.async.wait_group %0;" :: "n"(N) : "memory");
}

__device__ __forceinline__ void ctr_arrive(unsigned* ctr) {
    asm volatile("red.release.gpu.global.add.u32 [%0], 1;" :: "l"(ctr) : "memory");
}
// poll by tid0 then block-wide sync
__device__ __forceinline__ void ctr_wait(unsigned* ctr, unsigned target) {
    if (threadIdx.x == 0) {
        unsigned v;
        do {
            asm volatile("ld.acquire.gpu.global.u32 %0, [%1];" : "=r"(v) : "l"(ctr) : "memory");
        } while ((int)(v - target) < 0);
    }
    __syncthreads();
}
__device__ __forceinline__ void ctr_bar(unsigned* ctr, unsigned target) {
    __threadfence();
    __syncthreads();
    if (threadIdx.x == 0) ctr_arrive(ctr);
    ctr_wait(ctr, target);
}

// ---------------- kernel 1: pack weights fp16 gate-interleaved + reset barriers ----------------
__global__ void pack_kernel(
    const float* __restrict__ Wgx, const float* __restrict__ Wgh,
    const float* __restrict__ Wix, const float* __restrict__ Wih,
    const float* __restrict__ Wfx, const float* __restrict__ Wfh,
    const float* __restrict__ Wox, const float* __restrict__ Woh,
    const float* __restrict__ bgx, const float* __restrict__ bgh,
    const float* __restrict__ bix, const float* __restrict__ bih,
    const float* __restrict__ bfx, const float* __restrict__ bfh,
    const float* __restrict__ box_, const float* __restrict__ boh,
    const float* __restrict__ Wph)
{
    int idx = blockIdx.x * blockDim.x + threadIdx.x;  // covers G4*HH exactly
    if (idx < 8 * 32) g_grp[idx] = 0;
    if (idx == 0) g_arrive = 0;
    if (idx < G4 * HH) {
        int n = idx >> 9, k = idx & 511;
        int gate = n & 3, j = n >> 2;
        const float* W = (gate == 0) ? Wgh : (gate == 1) ? Wih : (gate == 2) ? Wfh : Woh;
        g_W4h_h[idx] = __float2half_rn(W[j * HH + k]);
    }
    if (idx < G4 * II) {
        int n = idx >> 8, k = idx & 255;
        int gate = n & 3, j = n >> 2;
        const float* W = (gate == 0) ? Wgx : (gate == 1) ? Wix : (gate == 2) ? Wfx : Wox;
        g_W4x_h[idx] = __float2half_rn(W[j * II + k]);
    }
    if (idx < G4) {
        int gate = idx & 3, j = idx >> 2;
        const float* bx = (gate == 0) ? bgx : (gate == 1) ? bix : (gate == 2) ? bfx : box_;
        const float* bh = (gate == 0) ? bgh : (gate == 1) ? bih : (gate == 2) ? bfh : boh;
        g_bias4[idx] = bx[j] + bh[j];
    }
    if (idx < OO * HH) {
        g_Wp_h[idx] = __float2half_rn(Wph[idx]);
    }
}

// ---------------- kernel 1b: convert x to fp16 ----------------
__global__ void xconv_kernel(const float* __restrict__ x) {
    size_t i = ((size_t)blockIdx.x * PTHREADS + threadIdx.x) * 8;
    float4 a = *reinterpret_cast<const float4*>(x + i);
    float4 b = *reinterpret_cast<const float4*>(x + i + 4);
    __half2 h0 = __floats2half2_rn(a.x, a.y);
    __half2 h1 = __floats2half2_rn(a.z, a.w);
    __half2 h2 = __floats2half2_rn(b.x, b.y);
    __half2 h3 = __floats2half2_rn(b.z, b.w);
    uint4 o;
    o.x = *reinterpret_cast<uint32_t*>(&h0);
    o.y = *reinterpret_cast<uint32_t*>(&h1);
    o.z = *reinterpret_cast<uint32_t*>(&h2);
    o.w = *reinterpret_cast<uint32_t*>(&h3);
    *reinterpret_cast<uint4*>(g_Xh + i) = o;
}

// ---------------- kernel 2: x-projections (unchanged, working) ----------------
__global__ void __launch_bounds__(PTHREADS, 2) xproj_kernel() {
    extern __shared__ __align__(16) char dsm[];
    __half* sA = (__half*)dsm;                   // 64 x 264
    __half* sB = (__half*)(dsm + 64 * 264 * 2);  // 128 x 264

    const int tid = threadIdx.x;
    const int nt = blockIdx.x;         // 0..15
    const int mt = blockIdx.y;         // 0..4095
    const int s  = mt >> 3;
    const int b0 = (mt & 7) * 64;
    const int n0 = nt * 128;

#pragma unroll
    for (int i = 0; i < 8; i++) {
        int id = i * 256 + tid; int row = id >> 5; int c8 = (id & 31) * 8;
        *reinterpret_cast<uint4*>(sA + row * 264 + c8) =
            *reinterpret_cast<const uint4*>(g_Xh + ((size_t)(b0 + row) * SS + s) * II + c8);
    }
#pragma unroll
    for (int i = 0; i < 16; i++) {
        int id = i * 256 + tid; int row = id >> 5; int c8 = (id & 31) * 8;
        *reinterpret_cast<uint4*>(sB + row * 264 + c8) =
            *reinterpret_cast<const uint4*>(g_W4x_h + (size_t)(n0 + row) * II + c8);
    }
    __syncthreads();

    const int lane = tid & 31, warp = tid >> 5;
    const int m0w = (warp >> 2) * 32, n0w = (warp & 3) * 32;
    const int grp = lane >> 3, rl = lane & 7;
    const uint32_t sA32 = (uint32_t)__cvta_generic_to_shared(sA);
    const uint32_t sB32 = (uint32_t)__cvta_generic_to_shared(sB);
    uint32_t aAddr[2], bAddr[2];
#pragma unroll
    for (int mi = 0; mi < 2; mi++) {
        int row = m0w + mi * 16 + (grp & 1) * 8 + rl;
        aAddr[mi] = sA32 + (row * 264 + (grp >> 1) * 8) * 2;
    }
#pragma unroll
    for (int nj = 0; nj < 2; nj++) {
        int row = n0w + nj * 16 + (grp >> 1) * 8 + rl;
        bAddr[nj] = sB32 + (row * 264 + (grp & 1) * 8) * 2;
    }

    float acc[2][4][4] = {};
#pragma unroll
    for (int kk = 0; kk < II; kk += 16) {
        uint32_t a[2][4], b[2][4];
        ldsm4(a[0], aAddr[0] + kk * 2);
        ldsm4(a[1], aAddr[1] + kk * 2);
        ldsm4(b[0], bAddr[0] + kk * 2);
        ldsm4(b[1], bAddr[1] + kk * 2);
#pragma unroll
        for (int mi = 0; mi < 2; mi++)
#pragma unroll
            for (int ni = 0; ni < 4; ni++)
                mma16816(acc[mi][ni], a[mi], b[ni >> 1] + (ni & 1) * 2);
    }

    const int gq = lane >> 2, t4 = lane & 3;
    __half* XPb = g_XP + (size_t)s * BB * G4;
#pragma unroll
    for (int mi = 0; mi < 2; mi++) {
#pragma unroll
        for (int ni = 0; ni < 4; ni++) {
            int r = m0w + mi * 16 + gq;
            int c = n0w + ni * 8 + t4 * 2;
            float bv0 = g_bias4[n0 + c], bv1 = g_bias4[n0 + c + 1];
            *reinterpret_cast<__half2*>(XPb + (size_t)(b0 + r) * G4 + n0 + c) =
                __floats2half2_rn(acc[mi][ni][0] + bv0, acc[mi][ni][1] + bv1);
            *reinterpret_cast<__half2*>(XPb + (size_t)(b0 + r + 8) * G4 + n0 + c) =
                __floats2half2_rn(acc[mi][ni][2] + bv0, acc[mi][ni][3] + bv1);
        }
    }
}

// ---------------- lstm device helpers ----------------
// GEMM: C[64x64] += A[64x512] * B[64x512]^T, 16 warps in 4x4 grid (warp tile 16x16)
__device__ __forceinline__ void gemm64(float (&acc)[2][4], uint32_t aAddr, uint32_t bAddr) {
#pragma unroll 8
    for (int kk = 0; kk < HH; kk += 16) {
        uint32_t a[4], b[4];
        ldsm4(a, aAddr + kk * 2);
        ldsm4(b, bAddr + kk * 2);
        mma16816(acc[0], a, b);
        mma16816(acc[1], a, b + 2);
    }
}

// load 64x512-half tile into smem (stride LDA) via cp.async; 8 chunks/thread, 512 threads
__device__ __forceinline__ void load_tile_async(uint32_t sdst, const __half* gsrc, int tid) {
#pragma unroll
    for (int i = 0; i < 8; i++) {
        int id = i * 512 + tid; int row = id >> 6; int c8 = (id & 63) * 8;
        cpasync16(sdst + (row * LDA + c8) * 2, gsrc + (size_t)row * HH + c8);
    }
}

// early XP register loads (4 x half2 per group per thread)
__device__ __forceinline__ void load_xp(uint32_t (&xp)[4], const __half* XPs,
                                        int b0g, int n0, int m0w, int n0w, int gq, int t4) {
#pragma unroll
    for (int ni = 0; ni < 2; ni++) {
#pragma unroll
        for (int rh = 0; rh < 2; rh++) {
            const uint32_t* p = reinterpret_cast<const uint32_t*>(
                XPs + (size_t)(b0g + m0w + gq + rh * 8) * G4 + n0 + n0w + ni * 8 + t4 * 2);
            xp[ni * 2 + rh] = __ldg(p);
        }
    }
}

__device__ __forceinline__ void do_stage(float* stg, const float (&acc)[2][4],
                                         const uint32_t (&xp)[4],
                                         int m0w, int n0w, int gq, int t4) {
#pragma unroll
    for (int ni = 0; ni < 2; ni++) {
        int r = m0w + gq;
        int c = n0w + ni * 8 + t4 * 2;
        float2 lo = __half22float2(*reinterpret_cast<const __half2*>(&xp[ni * 2]));
        float2 hi = __half22float2(*reinterpret_cast<const __half2*>(&xp[ni * 2 + 1]));
        stg[r * 68 + c]           = acc[ni][0] + lo.x;
        stg[r * 68 + c + 1]       = acc[ni][1] + lo.y;
        stg[(r + 8) * 68 + c]     = acc[ni][2] + hi.x;
        stg[(r + 8) * 68 + c + 1] = acc[ni][3] + hi.y;
    }
}

// gates: 64 rows x 16 j per CTA-group; thread owns 2 adjacent j cells. C in registers.
__device__ __forceinline__ void do_gates(const float* stg, int tid, __half* hdst,
                                         int b0g, int nt, float& c0, float& c1, bool first) {
    int bl = tid >> 3;
    int j2 = (tid & 7) * 2;
    float4 v0 = *reinterpret_cast<const float4*>(stg + bl * 68 + j2 * 4);
    float4 v1 = *reinterpret_cast<const float4*>(stg + bl * 68 + j2 * 4 + 4);
    float gg0 = tanhfast(v0.x), iv0 = sigf(v0.y), fv0 = sigf(v0.z), ov0 = sigf(v0.w);
    float gg1 = tanhfast(v1.x), iv1 = sigf(v1.y), fv1 = sigf(v1.z), ov1 = sigf(v1.w);
    c0 = first ? gg0 * iv0 : fmaf(c0, fv0, gg0 * iv0);
    c1 = first ? gg1 * iv1 : fmaf(c1, fv1, gg1 * iv1);
    float h0 = tanhfast(c0) * ov0;
    float h1 = tanhfast(c1) * ov1;
    *reinterpret_cast<__half2*>(hdst + (size_t)(b0g + bl) * HH + nt * 16 + j2) =
        __floats2half2_rn(h0, h1);
}

// ---------------- kernel 3: persistent loop, 2 interleaved groups per CTA ----------------
__global__ void __launch_bounds__(LTHREADS) lstm_kernel(const float* __restrict__ bph,
                                                        float* __restrict__ out) {
    extern __shared__ __align__(16) char dsm[];
    __half* sW  = (__half*)dsm;                      // 64 x LDA (resident W slice, shared by both groups)
    __half* sAA = (__half*)(dsm + 64 * LDA * 2);     // group-A h tile / stage
    __half* sAB = (__half*)(dsm + 2 * 64 * LDA * 2); // group-B h tile / stage
    float* stgA = (float*)sAA;
    float* stgB = (float*)sAB;

    const int tid = threadIdx.x;
    const int cta = blockIdx.x;
    const int nt = cta & 31;        // 0..31, 64-col slice
    const int pt = cta >> 5;        // 0..3, group pair
    const int gA = pt * 2, gB = pt * 2 + 1;
    const int b0A = gA * 64, b0B = gB * 64;
    const int n0 = nt * 64;
    unsigned* ctrA = &g_grp[gA * 32];
    unsigned* ctrB = &g_grp[gB * 32];

    const uint32_t sW32  = (uint32_t)__cvta_generic_to_shared(sW);
    const uint32_t sAA32 = (uint32_t)__cvta_generic_to_shared(sAA);
    const uint32_t sAB32 = (uint32_t)__cvta_generic_to_shared(sAB);

    // resident W slice (64 rows of W4h for this nt)
    load_tile_async(sW32, g_W4h_h + (size_t)n0 * HH, tid);
    cpasync_commit();
    cpasync_waitg<0>();
    __syncthreads();

    const int lane = tid & 31, warp = tid >> 5;
    const int m0w = (warp >> 2) * 16;
    const int n0w = (warp & 3) * 16;
    const int grp = lane >> 3, rl = lane & 7;
    const int gq = lane >> 2, t4 = lane & 3;
    const uint32_t aOff = ((m0w + (grp & 1) * 8 + rl) * LDA + (grp >> 1) * 8) * 2;
    const uint32_t aAddrA = sAA32 + aOff;
    const uint32_t aAddrB = sAB32 + aOff;
    const uint32_t bAddr  = sW32 + ((n0w + (grp >> 1) * 8 + rl) * LDA + (grp & 1) * 8) * 2;

    float cA0 = 0.f, cA1 = 0.f, cB0 = 0.f, cB1 = 0.f;

    // ---- prologue: step 0 (h=0, gates from XP only) ----
    {
        uint32_t xpA[4], xpB[4];
        load_xp(xpA, g_XP, b0A, n0, m0w, n0w, gq, t4);
        load_xp(xpB, g_XP, b0B, n0, m0w, n0w, gq, t4);
        float zacc[2][4] = {};
        do_stage(stgA, zacc, xpA, m0w, n0w, gq, t4);
        do_stage(stgB, zacc, xpB, m0w, n0w, gq, t4);
        __syncthreads();
        do_gates(stgA, tid, g_Hh[1], b0A, nt, cA0, cA1, true);
        do_gates(stgB, tid, g_Hh[1], b0B, nt, cB0, cB1, true);
        __threadfence();
        __syncthreads();
        if (tid == 0) { ctr_arrive(ctrA); ctr_arrive(ctrB); }
        ctr_wait(ctrA, 32);
        load_tile_async(sAA32, g_Hh[1] + (size_t)b0A * HH, tid);
        cpasync_commit();   // pending: [hA(1)]
    }

    // ---- main loop ----
    for (int s = 1; s < SS; ++s) {
        __syncthreads();  // prior stage_B fully consumed before h_B overwrite below
        const __half* XPs = g_XP + (size_t)s * BB * G4;
        uint32_t xpA[4], xpB[4];
        load_xp(xpA, XPs, b0A, n0, m0w, n0w, gq, t4);
        load_xp(xpB, XPs, b0B, n0, m0w, n0w, gq, t4);

        ctr_wait(ctrB, (unsigned)s * 32);
        load_tile_async(sAB32, g_Hh[s & 1] + (size_t)b0B * HH, tid);
        cpasync_commit();   // pending: [hA(s), hB(s)]

        // ---- group A ----
        cpasync_waitg<1>();  // hA(s) complete
        __syncthreads();
        float accA[2][4] = {};
        gemm64(accA, aAddrA, bAddr);
        __syncthreads();
        do_stage(stgA, accA, xpA, m0w, n0w, gq, t4);
        __syncthreads();
        do_gates(stgA, tid, g_Hh[(s + 1) & 1], b0A, nt, cA0, cA1, false);
        __threadfence();
        __syncthreads();
        if (tid == 0) ctr_arrive(ctrA);

        // ---- group B ----
        cpasync_waitg<0>();  // hB(s) complete
        __syncthreads();
        float accB[2][4] = {};
        gemm64(accB, aAddrB, bAddr);
        __syncthreads();
        do_stage(stgB, accB, xpB, m0w, n0w, gq, t4);
        __syncthreads();
        do_gates(stgB, tid, g_Hh[(s + 1) & 1], b0B, nt, cB0, cB1, false);
        __threadfence();
        __syncthreads();
        if (tid == 0) ctr_arrive(ctrB);

        // prefetch next hA under the gap to next iteration
        if (s < SS - 1) {
            ctr_wait(ctrA, (unsigned)(s + 1) * 32);
            load_tile_async(sAA32, g_Hh[(s + 1) & 1] + (size_t)b0A * HH, tid);
            cpasync_commit();   // pending: [hA(s+1)]
        }
    }

    // ---- global barrier, then final projection (h(512) is in g_Hh[0]) ----
    ctr_bar(&g_arrive, NCTA2);

    if (cta < 32) {
        const int pb0 = (cta >> 2) * 64;   // 8 row tiles
        const int pn0 = (cta & 3) * 64;    // 4 col tiles
#pragma unroll
        for (int i = 0; i < 8; i++) {
            int id = i * 512 + tid; int row = id >> 6; int c8 = (id & 63) * 8;
            *reinterpret_cast<uint4*>(sW + row * LDA + c8) =
                *reinterpret_cast<const uint4*>(g_Wp_h + (size_t)(pn0 + row) * HH + c8);
            *reinterpret_cast<uint4*>(sAA + row * LDA + c8) =
                *reinterpret_cast<const uint4*>(g_Hh[0] + (size_t)(pb0 + row) * HH + c8);
        }
        __syncthreads();

        float acc[2][4] = {};
        gemm64(acc, aAddrA, bAddr);
#pragma unroll
        for (int ni = 0; ni < 2; ni++) {
            int r  = m0w + gq;
            int cl = n0w + ni * 8 + t4 * 2;
            float bv0 = bph[pn0 + cl], bv1 = bph[pn0 + cl + 1];
            out[(size_t)(pb0 + r) * OO + pn0 + cl]         = acc[ni][0] + bv0;
            out[(size_t)(pb0 + r) * OO + pn0 + cl + 1]     = acc[ni][1] + bv1;
            out[(size_t)(pb0 + r + 8) * OO + pn0 + cl]     = acc[ni][2] + bv0;
            out[(size_t)(pb0 + r + 8) * OO + pn0 + cl + 1] = acc[ni][3] + bv1;
        }
    }
}

// ---------------- launch ----------------
extern "C" void kernel_launch(void* const* d_in, const int* in_sizes, int n_in,
                              void* d_out, int out_size) {
    (void)in_sizes; (void)n_in; (void)out_size;
    const float* x   = (const float*)d_in[0];
    const float* Wgx = (const float*)d_in[1];
    const float* bgx = (const float*)d_in[2];
    const float* Wgh = (const float*)d_in[3];
    const float* bgh = (const float*)d_in[4];
    const float* Wix = (const float*)d_in[5];
    const float* bix = (const float*)d_in[6];
    const float* Wih = (const float*)d_in[7];
    const float* bih = (const float*)d_in[8];
    const float* Wfx = (const float*)d_in[9];
    const float* bfx = (const float*)d_in[10];
    const float* Wfh = (const float*)d_in[11];
    const float* bfh = (const float*)d_in[12];
    const float* Wox = (const float*)d_in[13];
    const float* box_ = (const float*)d_in[14];
    const float* Woh = (const float*)d_in[15];
    const float* boh = (const float*)d_in[16];
    const float* Wph = (const float*)d_in[17];
    const float* bph = (const float*)d_in[18];

    cudaFuncSetAttribute((const void*)xproj_kernel,
                         cudaFuncAttributeMaxDynamicSharedMemorySize, XPROJ_SMEM);
    cudaFuncSetAttribute((const void*)lstm_kernel,
                         cudaFuncAttributeMaxDynamicSharedMemorySize, LSTM_SMEM);

    pack_kernel<<<(G4 * HH) / PTHREADS, PTHREADS>>>(
        Wgx, Wgh, Wix, Wih, Wfx, Wfh, Wox, Woh,
        bgx, bgh, bix, bih, bfx, bfh, box_, boh, Wph);

    xconv_kernel<<<(BB * SS * II) / (PTHREADS * 8), PTHREADS>>>(x);

    dim3 g1(16, SS * (BB / 64));
    xproj_kernel<<<g1, PTHREADS, XPROJ_SMEM>>>();

    lstm_kernel<<<NCTA2, LTHREADS, LSTM_SMEM>>>(bph, (float*)d_out);
}

// round 8
// speedup vs baseline: 1.3478x; 1.3478x over previous
#include <cuda_runtime.h>
#include <cuda_fp16.h>
#include <cstdint>

// Problem dims
#define BB 512
#define SS 512
#define II 256
#define HH 512
#define OO 256
#define G4 2048   // 4*HH, gate-interleaved: n = j*4 + gate, order (g,i,f,o)

#define PTHREADS 256
#define LTHREADS 256
#define NCTA3 256   // 8 groups x 32 nt (64 gate-cols each)

#define LDW 520     // smem row stride (halfs) for W slice
#define LDH 136     // smem row stride (halfs) for h chunk (k=128)
#define HCHUNK_B (64 * LDH * 2)                    // 17,408 B per h buffer
#define LSTM_SMEM  (64 * LDW * 2 + 2 * HCHUNK_B)  // 66,560 + 34,816 = 101,376 B
#define XPROJ_SMEM ((64 + 128) * 264 * 2)          // 101,376 B (2 CTAs/SM)

// ---------------- device-global scratch (no cudaMalloc; keep < ~1.5 GB) ----------------
__device__ __align__(16) __half g_W4x_h[(size_t)G4 * II];
__device__ __align__(16) __half g_W4h_h[(size_t)G4 * HH];
__device__ __align__(16) __half g_Wp_h[(size_t)OO * HH];
__device__ float  g_bias4[G4];
__device__ __align__(16) __half g_Xh[(size_t)BB * SS * II];  // x fp16 (128 MB)
__device__ __align__(16) __half g_XP[(size_t)SS * BB * G4];  // x-projections + bias (1 GB)
__device__ __align__(16) __half g_Hh[2][(size_t)BB * HH];
__device__ unsigned g_grp[8 * 32];   // per-group barrier counters, 128B apart
__device__ unsigned g_arrive;        // global barrier before projection

// ---------------- helpers ----------------
__device__ __forceinline__ float sigf(float x) {
    return __fdividef(1.f, 1.f + __expf(-x));
}
__device__ __forceinline__ float tanhfast(float x) {
    x = fminf(15.f, fmaxf(-15.f, x));
    float t = __expf(2.f * x);
    return __fdividef(t - 1.f, t + 1.f);
}
__device__ __forceinline__ void ldsm4(uint32_t* r, uint32_t addr) {
    asm volatile("ldmatrix.sync.aligned.m8n8.x4.shared.b16 {%0,%1,%2,%3}, [%4];"
                 : "=r"(r[0]), "=r"(r[1]), "=r"(r[2]), "=r"(r[3]) : "r"(addr));
}
__device__ __forceinline__ void mma16816(float* d, const uint32_t* a, const uint32_t* b) {
    asm volatile("mma.sync.aligned.m16n8k16.row.col.f32.f16.f16.f32 "
                 "{%0,%1,%2,%3},{%4,%5,%6,%7},{%8,%9},{%0,%1,%2,%3};"
                 : "+f"(d[0]), "+f"(d[1]), "+f"(d[2]), "+f"(d[3])
                 : "r"(a[0]), "r"(a[1]), "r"(a[2]), "r"(a[3]), "r"(b[0]), "r"(b[1]));
}
__device__ __forceinline__ void cpasync16(uint32_t dst, const void* src) {
    asm volatile("cp.async.cg.shared.global [%0], [%1], 16;" :: "r"(dst), "l"(src));
}
__device__ __forceinline__ void cpasync_commit() {
    asm volatile("cp.async.commit_group;" ::: "memory");
}
template <int N>
__device__ __forceinline__ void cpasync_waitg() {
    asm volatile("cp.async.wait_group %0;" :: "n"(N) : "memory");
}

__device__ __forceinline__ void ctr_arrive(unsigned* ctr) {
    asm volatile("red.release.gpu.global.add.u32 [%0], 1;" :: "l"(ctr) : "memory");
}
__device__ __forceinline__ void ctr_wait(unsigned* ctr, unsigned target) {
    if (threadIdx.x == 0) {
        unsigned v;
        do {
            asm volatile("ld.acquire.gpu.global.u32 %0, [%1];" : "=r"(v) : "l"(ctr) : "memory");
        } while ((int)(v - target) < 0);
    }
    __syncthreads();
}
__device__ __forceinline__ void ctr_bar(unsigned* ctr, unsigned target) {
    __threadfence();
    __syncthreads();
    if (threadIdx.x == 0) ctr_arrive(ctr);
    ctr_wait(ctr, target);
}

// ---------------- kernel 1: pack weights fp16 gate-interleaved + reset barriers ----------------
__global__ void pack_kernel(
    const float* __restrict__ Wgx, const float* __restrict__ Wgh,
    const float* __restrict__ Wix, const float* __restrict__ Wih,
    const float* __restrict__ Wfx, const float* __restrict__ Wfh,
    const float* __restrict__ Wox, const float* __restrict__ Woh,
    const float* __restrict__ bgx, const float* __restrict__ bgh,
    const float* __restrict__ bix, const float* __restrict__ bih,
    const float* __restrict__ bfx, const float* __restrict__ bfh,
    const float* __restrict__ box_, const float* __restrict__ boh,
    const float* __restrict__ Wph)
{
    int idx = blockIdx.x * blockDim.x + threadIdx.x;  // covers G4*HH exactly
    if (idx < 8 * 32) g_grp[idx] = 0;
    if (idx == 0) g_arrive = 0;
    if (idx < G4 * HH) {
        int n = idx >> 9, k = idx & 511;
        int gate = n & 3, j = n >> 2;
        const float* W = (gate == 0) ? Wgh : (gate == 1) ? Wih : (gate == 2) ? Wfh : Woh;
        g_W4h_h[idx] = __float2half_rn(W[j * HH + k]);
    }
    if (idx < G4 * II) {
        int n = idx >> 8, k = idx & 255;
        int gate = n & 3, j = n >> 2;
        const float* W = (gate == 0) ? Wgx : (gate == 1) ? Wix : (gate == 2) ? Wfx : Wox;
        g_W4x_h[idx] = __float2half_rn(W[j * II + k]);
    }
    if (idx < G4) {
        int gate = idx & 3, j = idx >> 2;
        const float* bx = (gate == 0) ? bgx : (gate == 1) ? bix : (gate == 2) ? bfx : box_;
        const float* bh = (gate == 0) ? bgh : (gate == 1) ? bih : (gate == 2) ? bfh : boh;
        g_bias4[idx] = bx[j] + bh[j];
    }
    if (idx < OO * HH) {
        g_Wp_h[idx] = __float2half_rn(Wph[idx]);
    }
}

// ---------------- kernel 1b: convert x to fp16 ----------------
__global__ void xconv_kernel(const float* __restrict__ x) {
    size_t i = ((size_t)blockIdx.x * PTHREADS + threadIdx.x) * 8;
    float4 a = *reinterpret_cast<const float4*>(x + i);
    float4 b = *reinterpret_cast<const float4*>(x + i + 4);
    __half2 h0 = __floats2half2_rn(a.x, a.y);
    __half2 h1 = __floats2half2_rn(a.z, a.w);
    __half2 h2 = __floats2half2_rn(b.x, b.y);
    __half2 h3 = __floats2half2_rn(b.z, b.w);
    uint4 o;
    o.x = *reinterpret_cast<uint32_t*>(&h0);
    o.y = *reinterpret_cast<uint32_t*>(&h1);
    o.z = *reinterpret_cast<uint32_t*>(&h2);
    o.w = *reinterpret_cast<uint32_t*>(&h3);
    *reinterpret_cast<uint4*>(g_Xh + i) = o;
}

// ---------------- kernel 2: x-projections (unchanged, working) ----------------
__global__ void __launch_bounds__(PTHREADS, 2) xproj_kernel() {
    extern __shared__ __align__(16) char dsm[];
    __half* sA = (__half*)dsm;                   // 64 x 264
    __half* sB = (__half*)(dsm + 64 * 264 * 2);  // 128 x 264

    const int tid = threadIdx.x;
    const int nt = blockIdx.x;         // 0..15
    const int mt = blockIdx.y;         // 0..4095
    const int s  = mt >> 3;
    const int b0 = (mt & 7) * 64;
    const int n0 = nt * 128;

#pragma unroll
    for (int i = 0; i < 8; i++) {
        int id = i * 256 + tid; int row = id >> 5; int c8 = (id & 31) * 8;
        *reinterpret_cast<uint4*>(sA + row * 264 + c8) =
            *reinterpret_cast<const uint4*>(g_Xh + ((size_t)(b0 + row) * SS + s) * II + c8);
    }
#pragma unroll
    for (int i = 0; i < 16; i++) {
        int id = i * 256 + tid; int row = id >> 5; int c8 = (id & 31) * 8;
        *reinterpret_cast<uint4*>(sB + row * 264 + c8) =
            *reinterpret_cast<const uint4*>(g_W4x_h + (size_t)(n0 + row) * II + c8);
    }
    __syncthreads();

    const int lane = tid & 31, warp = tid >> 5;
    const int m0w = (warp >> 2) * 32, n0w = (warp & 3) * 32;
    const int grp = lane >> 3, rl = lane & 7;
    const uint32_t sA32 = (uint32_t)__cvta_generic_to_shared(sA);
    const uint32_t sB32 = (uint32_t)__cvta_generic_to_shared(sB);
    uint32_t aAddr[2], bAddr[2];
#pragma unroll
    for (int mi = 0; mi < 2; mi++) {
        int row = m0w + mi * 16 + (grp & 1) * 8 + rl;
        aAddr[mi] = sA32 + (row * 264 + (grp >> 1) * 8) * 2;
    }
#pragma unroll
    for (int nj = 0; nj < 2; nj++) {
        int row = n0w + nj * 16 + (grp >> 1) * 8 + rl;
        bAddr[nj] = sB32 + (row * 264 + (grp & 1) * 8) * 2;
    }

    float acc[2][4][4] = {};
#pragma unroll
    for (int kk = 0; kk < II; kk += 16) {
        uint32_t a[2][4], b[2][4];
        ldsm4(a[0], aAddr[0] + kk * 2);
        ldsm4(a[1], aAddr[1] + kk * 2);
        ldsm4(b[0], bAddr[0] + kk * 2);
        ldsm4(b[1], bAddr[1] + kk * 2);
#pragma unroll
        for (int mi = 0; mi < 2; mi++)
#pragma unroll
            for (int ni = 0; ni < 4; ni++)
                mma16816(acc[mi][ni], a[mi], b[ni >> 1] + (ni & 1) * 2);
    }

    const int gq = lane >> 2, t4 = lane & 3;
    __half* XPb = g_XP + (size_t)s * BB * G4;
#pragma unroll
    for (int mi = 0; mi < 2; mi++) {
#pragma unroll
        for (int ni = 0; ni < 4; ni++) {
            int r = m0w + mi * 16 + gq;
            int c = n0w + ni * 8 + t4 * 2;
            float bv0 = g_bias4[n0 + c], bv1 = g_bias4[n0 + c + 1];
            *reinterpret_cast<__half2*>(XPb + (size_t)(b0 + r) * G4 + n0 + c) =
                __floats2half2_rn(acc[mi][ni][0] + bv0, acc[mi][ni][1] + bv1);
            *reinterpret_cast<__half2*>(XPb + (size_t)(b0 + r + 8) * G4 + n0 + c) =
                __floats2half2_rn(acc[mi][ni][2] + bv0, acc[mi][ni][3] + bv1);
        }
    }
}

// ---------------- lstm device helpers ----------------
// issue cp.async for one 64x128-half h chunk into smem buffer (stride LDH)
__device__ __forceinline__ void load_hchunk(uint32_t sdst, const __half* gsrc_base,
                                            int kbase, int tid) {
#pragma unroll
    for (int i = 0; i < 4; i++) {
        int id = i * 256 + tid; int row = id >> 4; int c8 = (id & 15) * 8;
        cpasync16(sdst + (row * LDH + c8) * 2,
                  gsrc_base + (size_t)row * HH + kbase + c8);
    }
}

// one k=128 chunk of the 64x64 GEMM (8 warps, warp tile 16x32)
__device__ __forceinline__ void gemm_chunk(float (&acc)[4][4], uint32_t aAddr,
                                           const uint32_t (&bAddr)[2], int kbase) {
#pragma unroll
    for (int kk = 0; kk < 128; kk += 16) {
        uint32_t a[4], b[2][4];
        ldsm4(a, aAddr + kk * 2);
        ldsm4(b[0], bAddr[0] + (kbase + kk) * 2);
        ldsm4(b[1], bAddr[1] + (kbase + kk) * 2);
#pragma unroll
        for (int ni = 0; ni < 4; ni++)
            mma16816(acc[ni], a, b[ni >> 1] + (ni & 1) * 2);
    }
}

// full 64x64x512 GEMM streaming h from gmem through double-buffered chunks
__device__ __forceinline__ void gemm_streamed(float (&acc)[4][4], const __half* hsrc,
                                              uint32_t sH32, const uint32_t aAddr[2],
                                              const uint32_t (&bAddr)[2], int tid) {
    load_hchunk(sH32, hsrc, 0, tid);               cpasync_commit();
    load_hchunk(sH32 + HCHUNK_B, hsrc, 128, tid);  cpasync_commit();
#pragma unroll
    for (int c = 0; c < 4; c++) {
        if (c < 3) cpasync_waitg<1>(); else cpasync_waitg<0>();
        __syncthreads();
        gemm_chunk(acc, aAddr[c & 1], bAddr, c * 128);
        if (c < 2) {
            __syncthreads();
            load_hchunk(sH32 + (c & 1) * HCHUNK_B, hsrc, (c + 2) * 128, tid);
            cpasync_commit();
        }
    }
    __syncthreads();
}

// XP register prefetch: 8 half2 per thread
__device__ __forceinline__ void load_xp(uint32_t (&xp)[8], const __half* XPs,
                                        int b0, int n0, int m0w, int n0w, int gq, int t4) {
#pragma unroll
    for (int ni = 0; ni < 4; ni++) {
#pragma unroll
        for (int rh = 0; rh < 2; rh++) {
            const uint32_t* p = reinterpret_cast<const uint32_t*>(
                XPs + (size_t)(b0 + m0w + gq + rh * 8) * G4 + n0 + n0w + ni * 8 + t4 * 2);
            xp[ni * 2 + rh] = __ldg(p);
        }
    }
}

__device__ __forceinline__ void do_stage(float* stg, const float (&acc)[4][4],
                                         const uint32_t (&xp)[8],
                                         int m0w, int n0w, int gq, int t4) {
#pragma unroll
    for (int ni = 0; ni < 4; ni++) {
        int r = m0w + gq;
        int c = n0w + ni * 8 + t4 * 2;
        float2 lo = __half22float2(*reinterpret_cast<const __half2*>(&xp[ni * 2]));
        float2 hi = __half22float2(*reinterpret_cast<const __half2*>(&xp[ni * 2 + 1]));
        stg[r * 68 + c]           = acc[ni][0] + lo.x;
        stg[r * 68 + c + 1]       = acc[ni][1] + lo.y;
        stg[(r + 8) * 68 + c]     = acc[ni][2] + hi.x;
        stg[(r + 8) * 68 + c + 1] = acc[ni][3] + hi.y;
    }
}

// gates for 64 rows x 16 j (64 gate-cols); thread owns row bl, j-block j4 (4 j's); C in regs
__device__ __forceinline__ void do_gates(const float* stg, int tid, __half* hdst,
                                         int b0, int nt, float (&C)[4], bool first) {
    int bl = tid >> 2;
    int j4 = tid & 3;
    __half hv[4];
#pragma unroll
    for (int jj = 0; jj < 4; jj++) {
        float4 v = *reinterpret_cast<const float4*>(stg + bl * 68 + j4 * 16 + jj * 4);
        float gg = tanhfast(v.x), iv = sigf(v.y), fv = sigf(v.z), ov = sigf(v.w);
        C[jj] = first ? gg * iv : fmaf(C[jj], fv, gg * iv);
        hv[jj] = __float2half_rn(tanhfast(C[jj]) * ov);
    }
    *reinterpret_cast<uint2*>(hdst + (size_t)(b0 + bl) * HH + nt * 16 + j4 * 4) =
        *reinterpret_cast<uint2*>(hv);
}

// ---------------- kernel 3: persistent loop, 1 chain/CTA, 2 CTAs/SM ----------------
__global__ void __launch_bounds__(LTHREADS, 2) lstm_kernel(const float* __restrict__ bph,
                                                           float* __restrict__ out) {
    extern __shared__ __align__(16) char dsm[];
    __half* sW = (__half*)dsm;                   // 64 x LDW (resident W slice)
    __half* sH = (__half*)(dsm + 64 * LDW * 2);  // 2 x (64 x LDH) chunk buffers
    float*  stg = (float*)sH;                    // 64 x 68 floats = 17,408 B (= buffer 0)

    const int tid = threadIdx.x;
    const int cta = blockIdx.x;
    const int nt  = cta & 31;    // 64 gate-cols
    const int grp = cta >> 5;    // 0..7
    const int b0  = grp * 64;
    const int n0  = nt * 64;
    unsigned* ctr = &g_grp[grp * 32];

    const uint32_t sW32 = (uint32_t)__cvta_generic_to_shared(sW);
    const uint32_t sH32 = (uint32_t)__cvta_generic_to_shared(sH);

    // resident W slice: 64 rows x 512 halfs = 4096 uint4, 16/thread
#pragma unroll
    for (int i = 0; i < 16; i++) {
        int id = i * 256 + tid; int row = id >> 6; int c8 = (id & 63) * 8;
        cpasync16(sW32 + (row * LDW + c8) * 2, g_W4h_h + (size_t)(n0 + row) * HH + c8);
    }
    cpasync_commit();

    const int lane = tid & 31, warp = tid >> 5;
    const int m0w = (warp >> 1) * 16;   // 4 m x 2 n warp grid
    const int n0w = (warp & 1) * 32;
    const int lg = lane >> 3, rl = lane & 7;
    const int gq = lane >> 2, t4 = lane & 3;
    const uint32_t aOff = ((m0w + (lg & 1) * 8 + rl) * LDH + (lg >> 1) * 8) * 2;
    const uint32_t aAddr[2] = { sH32 + aOff, sH32 + HCHUNK_B + aOff };
    uint32_t bAddr[2];
#pragma unroll
    for (int nj = 0; nj < 2; nj++) {
        int row = n0w + nj * 16 + (lg >> 1) * 8 + rl;
        bAddr[nj] = sW32 + (row * LDW + (lg & 1) * 8) * 2;
    }

    float C[4];

    // ---- prologue: step 0 (h = 0) ----
    {
        uint32_t xp[8];
        load_xp(xp, g_XP, b0, n0, m0w, n0w, gq, t4);
        float zacc[4][4] = {};
        do_stage(stg, zacc, xp, m0w, n0w, gq, t4);
        __syncthreads();
        do_gates(stg, tid, g_Hh[1], b0, nt, C, true);
        __threadfence();
        __syncthreads();
        if (tid == 0) ctr_arrive(ctr);
    }
    cpasync_waitg<0>();   // W slice resident (also drains before chunk pipeline)

    // ---- main loop ----
    for (int s = 1; s < SS; ++s) {
        uint32_t xp[8];
        load_xp(xp, g_XP + (size_t)s * BB * G4, b0, n0, m0w, n0w, gq, t4);

        ctr_wait(ctr, (unsigned)s * 32);   // h(s) published by all 32 CTAs of this group

        float acc[4][4] = {};
        gemm_streamed(acc, g_Hh[s & 1] + (size_t)b0 * HH, sH32, aAddr, bAddr, tid);

        do_stage(stg, acc, xp, m0w, n0w, gq, t4);
        __syncthreads();
        do_gates(stg, tid, g_Hh[(s + 1) & 1], b0, nt, C, false);
        __threadfence();
        __syncthreads();
        if (tid == 0) ctr_arrive(ctr);
    }

    // ---- global barrier, then final projection (h(512) in g_Hh[0]) ----
    ctr_bar(&g_arrive, NCTA3);

    if (cta < 32) {
        const int pb0 = (cta >> 2) * 64;   // 8 row tiles
        const int pn0 = (cta & 3) * 64;    // 4 col tiles
#pragma unroll
        for (int i = 0; i < 16; i++) {
            int id = i * 256 + tid; int row = id >> 6; int c8 = (id & 63) * 8;
            *reinterpret_cast<uint4*>(sW + row * LDW + c8) =
                *reinterpret_cast<const uint4*>(g_Wp_h + (size_t)(pn0 + row) * HH + c8);
        }
        __syncthreads();

        float acc[4][4] = {};
        gemm_streamed(acc, g_Hh[0] + (size_t)pb0 * HH, sH32, aAddr, bAddr, tid);

#pragma unroll
        for (int ni = 0; ni < 4; ni++) {
            int r  = m0w + gq;
            int cl = n0w + ni * 8 + t4 * 2;
            float bv0 = bph[pn0 + cl], bv1 = bph[pn0 + cl + 1];
            out[(size_t)(pb0 + r) * OO + pn0 + cl]         = acc[ni][0] + bv0;
            out[(size_t)(pb0 + r) * OO + pn0 + cl + 1]     = acc[ni][1] + bv1;
            out[(size_t)(pb0 + r + 8) * OO + pn0 + cl]     = acc[ni][2] + bv0;
            out[(size_t)(pb0 + r + 8) * OO + pn0 + cl + 1] = acc[ni][3] + bv1;
        }
    }
}

// ---------------- launch ----------------
extern "C" void kernel_launch(void* const* d_in, const int* in_sizes, int n_in,
                              void* d_out, int out_size) {
    (void)in_sizes; (void)n_in; (void)out_size;
    const float* x   = (const float*)d_in[0];
    const float* Wgx = (const float*)d_in[1];
    const float* bgx = (const float*)d_in[2];
    const float* Wgh = (const float*)d_in[3];
    const float* bgh = (const float*)d_in[4];
    const float* Wix = (const float*)d_in[5];
    const float* bix = (const float*)d_in[6];
    const float* Wih = (const float*)d_in[7];
    const float* bih = (const float*)d_in[8];
    const float* Wfx = (const float*)d_in[9];
    const float* bfx = (const float*)d_in[10];
    const float* Wfh = (const float*)d_in[11];
    const float* bfh = (const float*)d_in[12];
    const float* Wox = (const float*)d_in[13];
    const float* box_ = (const float*)d_in[14];
    const float* Woh = (const float*)d_in[15];
    const float* boh = (const float*)d_in[16];
    const float* Wph = (const float*)d_in[17];
    const float* bph = (const float*)d_in[18];

    cudaFuncSetAttribute((const void*)xproj_kernel,
                         cudaFuncAttributeMaxDynamicSharedMemorySize, XPROJ_SMEM);
    cudaFuncSetAttribute((const void*)lstm_kernel,
                         cudaFuncAttributeMaxDynamicSharedMemorySize, LSTM_SMEM);

    pack_kernel<<<(G4 * HH) / PTHREADS, PTHREADS>>>(
        Wgx, Wgh, Wix, Wih, Wfx, Wfh, Wox, Woh,
        bgx, bgh, bix, bih, bfx, bfh, box_, boh, Wph);

    xconv_kernel<<<(BB * SS * II) / (PTHREADS * 8), PTHREADS>>>(x);

    dim3 g1(16, SS * (BB / 64));
    xproj_kernel<<<g1, PTHREADS, XPROJ_SMEM>>>();

    lstm_kernel<<<NCTA3, LTHREADS, LSTM_SMEM>>>(bph, (float*)d_out);
}

// round 9
// speedup vs baseline: 1.3836x; 1.0266x over previous
#include <cuda_runtime.h>
#include <cuda_fp16.h>
#include <cstdint>

// Problem dims
#define BB 512
#define SS 512
#define II 256
#define HH 512
#define OO 256
#define G4 2048   // 4*HH, gate-interleaved: n = j*4 + gate, order (g,i,f,o)

#define PTHREADS 256
#define LTHREADS 256
#define NCTA3 256   // 8 groups x 32 nt (64 gate-cols each)

#define LDW 520     // smem row stride (halfs) for W slice
#define LDH 136     // smem row stride (halfs) for h chunk (k=128)
#define HCHUNK_B (64 * LDH * 2)                    // 17,408 B per h buffer
#define LSTM_SMEM  (64 * LDW * 2 + 2 * HCHUNK_B)  // 101,376 B (2 CTAs/SM)
#define XPROJ_SMEM ((64 + 128) * 264 * 2)          // 101,376 B (2 CTAs/SM)

// ---------------- device-global scratch (no cudaMalloc; keep < ~1.5 GB) ----------------
__device__ __align__(16) __half g_W4x_h[(size_t)G4 * II];
__device__ __align__(16) __half g_W4h_h[(size_t)G4 * HH];
__device__ __align__(16) __half g_Wp_h[(size_t)OO * HH];
__device__ float  g_bias4[G4];
__device__ __align__(16) __half g_Xh[(size_t)BB * SS * II];  // x fp16 (128 MB)
__device__ __align__(16) __half g_XP[(size_t)SS * BB * G4];  // x-projections + bias (1 GB)
__device__ __align__(16) __half g_Hh[2][(size_t)BB * HH];
__device__ unsigned g_sub[8 * 4 * 32];  // per-group, per-k-quarter counters, 128B apart
__device__ unsigned g_arrive;           // global barrier before projection

// ---------------- helpers ----------------
__device__ __forceinline__ float sigf(float x) {
    return __fdividef(1.f, 1.f + __expf(-x));
}
__device__ __forceinline__ float tanhfast(float x) {
    x = fminf(15.f, fmaxf(-15.f, x));
    float t = __expf(2.f * x);
    return __fdividef(t - 1.f, t + 1.f);
}
__device__ __forceinline__ void ldsm4(uint32_t* r, uint32_t addr) {
    asm volatile("ldmatrix.sync.aligned.m8n8.x4.shared.b16 {%0,%1,%2,%3}, [%4];"
                 : "=r"(r[0]), "=r"(r[1]), "=r"(r[2]), "=r"(r[3]) : "r"(addr));
}
__device__ __forceinline__ void mma16816(float* d, const uint32_t* a, const uint32_t* b) {
    asm volatile("mma.sync.aligned.m16n8k16.row.col.f32.f16.f16.f32 "
                 "{%0,%1,%2,%3},{%4,%5,%6,%7},{%8,%9},{%0,%1,%2,%3};"
                 : "+f"(d[0]), "+f"(d[1]), "+f"(d[2]), "+f"(d[3])
                 : "r"(a[0]), "r"(a[1]), "r"(a[2]), "r"(a[3]), "r"(b[0]), "r"(b[1]));
}
__device__ __forceinline__ void cpasync16(uint32_t dst, const void* src) {
    asm volatile("cp.async.cg.shared.global [%0], [%1], 16;" :: "r"(dst), "l"(src));
}
__device__ __forceinline__ void cpasync_commit() {
    asm volatile("cp.async.commit_group;" ::: "memory");
}
template <int N>
__device__ __forceinline__ void cpasync_waitg() {
    asm volatile("cp.async.wait_group %0;" :: "n"(N) : "memory");
}

__device__ __forceinline__ void ctr_arrive(unsigned* ctr) {
    asm volatile("red.release.gpu.global.add.u32 [%0], 1;" :: "l"(ctr) : "memory");
}
// tid0 polls, then block-wide sync
__device__ __forceinline__ void ctr_wait(unsigned* ctr, unsigned target) {
    if (threadIdx.x == 0) {
        unsigned v;
        do {
            asm volatile("ld.acquire.gpu.global.u32 %0, [%1];" : "=r"(v) : "l"(ctr) : "memory");
        } while ((int)(v - target) < 0);
    }
    __syncthreads();
}
__device__ __forceinline__ void ctr_bar(unsigned* ctr, unsigned target) {
    __threadfence();
    __syncthreads();
    if (threadIdx.x == 0) ctr_arrive(ctr);
    ctr_wait(ctr, target);
}

// ---------------- kernel 1: pack weights fp16 gate-interleaved + reset barriers ----------------
__global__ void pack_kernel(
    const float* __restrict__ Wgx, const float* __restrict__ Wgh,
    const float* __restrict__ Wix, const float* __restrict__ Wih,
    const float* __restrict__ Wfx, const float* __restrict__ Wfh,
    const float* __restrict__ Wox, const float* __restrict__ Woh,
    const float* __restrict__ bgx, const float* __restrict__ bgh,
    const float* __restrict__ bix, const float* __restrict__ bih,
    const float* __restrict__ bfx, const float* __restrict__ bfh,
    const float* __restrict__ box_, const float* __restrict__ boh,
    const float* __restrict__ Wph)
{
    int idx = blockIdx.x * blockDim.x + threadIdx.x;  // covers G4*HH exactly
    if (idx < 8 * 4 * 32) g_sub[idx] = 0;
    if (idx == 0) g_arrive = 0;
    if (idx < G4 * HH) {
        int n = idx >> 9, k = idx & 511;
        int gate = n & 3, j = n >> 2;
        const float* W = (gate == 0) ? Wgh : (gate == 1) ? Wih : (gate == 2) ? Wfh : Woh;
        g_W4h_h[idx] = __float2half_rn(W[j * HH + k]);
    }
    if (idx < G4 * II) {
        int n = idx >> 8, k = idx & 255;
        int gate = n & 3, j = n >> 2;
        const float* W = (gate == 0) ? Wgx : (gate == 1) ? Wix : (gate == 2) ? Wfx : Wox;
        g_W4x_h[idx] = __float2half_rn(W[j * II + k]);
    }
    if (idx < G4) {
        int gate = idx & 3, j = idx >> 2;
        const float* bx = (gate == 0) ? bgx : (gate == 1) ? bix : (gate == 2) ? bfx : box_;
        const float* bh = (gate == 0) ? bgh : (gate == 1) ? bih : (gate == 2) ? bfh : boh;
        g_bias4[idx] = bx[j] + bh[j];
    }
    if (idx < OO * HH) {
        g_Wp_h[idx] = __float2half_rn(Wph[idx]);
    }
}

// ---------------- kernel 1b: convert x to fp16 ----------------
__global__ void xconv_kernel(const float* __restrict__ x) {
    size_t i = ((size_t)blockIdx.x * PTHREADS + threadIdx.x) * 8;
    float4 a = *reinterpret_cast<const float4*>(x + i);
    float4 b = *reinterpret_cast<const float4*>(x + i + 4);
    __half2 h0 = __floats2half2_rn(a.x, a.y);
    __half2 h1 = __floats2half2_rn(a.z, a.w);
    __half2 h2 = __floats2half2_rn(b.x, b.y);
    __half2 h3 = __floats2half2_rn(b.z, b.w);
    uint4 o;
    o.x = *reinterpret_cast<uint32_t*>(&h0);
    o.y = *reinterpret_cast<uint32_t*>(&h1);
    o.z = *reinterpret_cast<uint32_t*>(&h2);
    o.w = *reinterpret_cast<uint32_t*>(&h3);
    *reinterpret_cast<uint4*>(g_Xh + i) = o;
}

// ---------------- kernel 2: x-projections; W tile resident, loop over b-tiles ----------------
__global__ void __launch_bounds__(PTHREADS, 2) xproj_kernel() {
    extern __shared__ __align__(16) char dsm[];
    __half* sB = (__half*)dsm;                    // 128 x 264 (resident W4x slice)
    __half* sA = (__half*)(dsm + 128 * 264 * 2);  // 64 x 264 (x tile, reloaded per b-tile)

    const int tid = threadIdx.x;
    const int nt = blockIdx.x;   // 0..15, 128 gate-cols
    const int s  = blockIdx.y;   // 0..511
    const int n0 = nt * 128;

    const uint32_t sA32 = (uint32_t)__cvta_generic_to_shared(sA);
    const uint32_t sB32 = (uint32_t)__cvta_generic_to_shared(sB);

    // resident W slice: 128 rows x 256 halfs = 4096 x 16B, 16/thread
#pragma unroll
    for (int i = 0; i < 16; i++) {
        int id = i * 256 + tid; int row = id >> 5; int c8 = (id & 31) * 8;
        cpasync16(sB32 + (row * 264 + c8) * 2,
                  g_W4x_h + (size_t)(n0 + row) * II + c8);
    }
    cpasync_commit();

    const int lane = tid & 31, warp = tid >> 5;
    const int m0w = (warp >> 2) * 32, n0w = (warp & 3) * 32;
    const int grp = lane >> 3, rl = lane & 7;
    const int gq = lane >> 2, t4 = lane & 3;
    uint32_t aAddr[2], bAddr[2];
#pragma unroll
    for (int mi = 0; mi < 2; mi++) {
        int row = m0w + mi * 16 + (grp & 1) * 8 + rl;
        aAddr[mi] = sA32 + (row * 264 + (grp >> 1) * 8) * 2;
    }
#pragma unroll
    for (int nj = 0; nj < 2; nj++) {
        int row = n0w + nj * 16 + (grp >> 1) * 8 + rl;
        bAddr[nj] = sB32 + (row * 264 + (grp & 1) * 8) * 2;
    }

    // hoist bias (constant across b-tiles)
    float bv[4][2];
#pragma unroll
    for (int ni = 0; ni < 4; ni++) {
        int c = n0 + n0w + ni * 8 + t4 * 2;
        bv[ni][0] = g_bias4[c];
        bv[ni][1] = g_bias4[c + 1];
    }

    __half* XPb = g_XP + (size_t)s * BB * G4;

    for (int bt = 0; bt < 8; ++bt) {
        const int b0 = bt * 64;
        // x tile: 64 rows x 256 halfs = 2048 x 16B, 8/thread
#pragma unroll
        for (int i = 0; i < 8; i++) {
            int id = i * 256 + tid; int row = id >> 5; int c8 = (id & 31) * 8;
            cpasync16(sA32 + (row * 264 + c8) * 2,
                      g_Xh + ((size_t)(b0 + row) * SS + s) * II + c8);
        }
        cpasync_commit();
        cpasync_waitg<0>();   // first iter also drains the W load
        __syncthreads();

        float acc[2][4][4] = {};
#pragma unroll
        for (int kk = 0; kk < II; kk += 16) {
            uint32_t a[2][4], b[2][4];
            ldsm4(a[0], aAddr[0] + kk * 2);
            ldsm4(a[1], aAddr[1] + kk * 2);
            ldsm4(b[0], bAddr[0] + kk * 2);
            ldsm4(b[1], bAddr[1] + kk * 2);
#pragma unroll
            for (int mi = 0; mi < 2; mi++)
#pragma unroll
                for (int ni = 0; ni < 4; ni++)
                    mma16816(acc[mi][ni], a[mi], b[ni >> 1] + (ni & 1) * 2);
        }

#pragma unroll
        for (int mi = 0; mi < 2; mi++) {
#pragma unroll
            for (int ni = 0; ni < 4; ni++) {
                int r = m0w + mi * 16 + gq;
                int c = n0w + ni * 8 + t4 * 2;
                *reinterpret_cast<__half2*>(XPb + (size_t)(b0 + r) * G4 + n0 + c) =
                    __floats2half2_rn(acc[mi][ni][0] + bv[ni][0], acc[mi][ni][1] + bv[ni][1]);
                *reinterpret_cast<__half2*>(XPb + (size_t)(b0 + r + 8) * G4 + n0 + c) =
                    __floats2half2_rn(acc[mi][ni][2] + bv[ni][0], acc[mi][ni][3] + bv[ni][1]);
            }
        }
        __syncthreads();  // sA reads done before next b-tile overwrites
    }
}

// ---------------- lstm device helpers ----------------
__device__ __forceinline__ void load_hchunk(uint32_t sdst, const __half* gsrc_base,
                                            int kbase, int tid) {
#pragma unroll
    for (int i = 0; i < 4; i++) {
        int id = i * 256 + tid; int row = id >> 4; int c8 = (id & 15) * 8;
        cpasync16(sdst + (row * LDH + c8) * 2,
                  gsrc_base + (size_t)row * HH + kbase + c8);
    }
}

// one k=128 chunk of the 64x64 GEMM (8 warps, warp tile 16x32)
__device__ __forceinline__ void gemm_chunk(float (&acc)[4][4], uint32_t aAddr,
                                           const uint32_t (&bAddr)[2], int kbase) {
#pragma unroll
    for (int kk = 0; kk < 128; kk += 16) {
        uint32_t a[4], b[2][4];
        ldsm4(a, aAddr + kk * 2);
        ldsm4(b[0], bAddr[0] + (kbase + kk) * 2);
        ldsm4(b[1], bAddr[1] + (kbase + kk) * 2);
#pragma unroll
        for (int ni = 0; ni < 4; ni++)
            mma16816(acc[ni], a, b[ni >> 1] + (ni & 1) * 2);
    }
}

// full 64x64x512 GEMM streaming h through double-buffered chunks (projection path)
__device__ __forceinline__ void gemm_streamed(float (&acc)[4][4], const __half* hsrc,
                                              uint32_t sH32, const uint32_t aAddr[2],
                                              const uint32_t (&bAddr)[2], int tid) {
    load_hchunk(sH32, hsrc, 0, tid);               cpasync_commit();
    load_hchunk(sH32 + HCHUNK_B, hsrc, 128, tid);  cpasync_commit();
#pragma unroll
    for (int c = 0; c < 4; c++) {
        if (c < 3) cpasync_waitg<1>(); else cpasync_waitg<0>();
        __syncthreads();
        gemm_chunk(acc, aAddr[c & 1], bAddr, c * 128);
        if (c < 2) {
            __syncthreads();
            load_hchunk(sH32 + (c & 1) * HCHUNK_B, hsrc, (c + 2) * 128, tid);
            cpasync_commit();
        }
    }
    __syncthreads();
}

// XP register prefetch: 8 half2 per thread
__device__ __forceinline__ void load_xp(uint32_t (&xp)[8], const __half* XPs,
                                        int b0, int n0, int m0w, int n0w, int gq, int t4) {
#pragma unroll
    for (int ni = 0; ni < 4; ni++) {
#pragma unroll
        for (int rh = 0; rh < 2; rh++) {
            const uint32_t* p = reinterpret_cast<const uint32_t*>(
                XPs + (size_t)(b0 + m0w + gq + rh * 8) * G4 + n0 + n0w + ni * 8 + t4 * 2);
            xp[ni * 2 + rh] = __ldg(p);
        }
    }
}

__device__ __forceinline__ void do_stage(float* stg, const float (&acc)[4][4],
                                         const uint32_t (&xp)[8],
                                         int m0w, int n0w, int gq, int t4) {
#pragma unroll
    for (int ni = 0; ni < 4; ni++) {
        int r = m0w + gq;
        int c = n0w + ni * 8 + t4 * 2;
        float2 lo = __half22float2(*reinterpret_cast<const __half2*>(&xp[ni * 2]));
        float2 hi = __half22float2(*reinterpret_cast<const __half2*>(&xp[ni * 2 + 1]));
        stg[r * 68 + c]           = acc[ni][0] + lo.x;
        stg[r * 68 + c + 1]       = acc[ni][1] + lo.y;
        stg[(r + 8) * 68 + c]     = acc[ni][2] + hi.x;
        stg[(r + 8) * 68 + c + 1] = acc[ni][3] + hi.y;
    }
}

// gates for 64 rows x 16 j; thread owns row bl, 4 j's; C in regs
__device__ __forceinline__ void do_gates(const float* stg, int tid, __half* hdst,
                                         int b0, int nt, float (&C)[4], bool first) {
    int bl = tid >> 2;
    int j4 = tid & 3;
    __half hv[4];
#pragma unroll
    for (int jj = 0; jj < 4; jj++) {
        float4 v = *reinterpret_cast<const float4*>(stg + bl * 68 + j4 * 16 + jj * 4);
        float gg = tanhfast(v.x), iv = sigf(v.y), fv = sigf(v.z), ov = sigf(v.w);
        C[jj] = first ? gg * iv : fmaf(C[jj], fv, gg * iv);
        hv[jj] = __float2half_rn(tanhfast(C[jj]) * ov);
    }
    *reinterpret_cast<uint2*>(hdst + (size_t)(b0 + bl) * HH + nt * 16 + j4 * 4) =
        *reinterpret_cast<uint2*>(hv);
}

// ---------------- kernel 3: persistent loop, quartered sub-barriers ----------------
__global__ void __launch_bounds__(LTHREADS, 2) lstm_kernel(const float* __restrict__ bph,
                                                           float* __restrict__ out) {
    extern __shared__ __align__(16) char dsm[];
    __half* sW = (__half*)dsm;                   // 64 x LDW (resident W slice)
    __half* sH = (__half*)(dsm + 64 * LDW * 2);  // 2 x (64 x LDH) chunk buffers
    float*  stg = (float*)sH;                    // 64 x 68 floats (= buffer 0)

    const int tid = threadIdx.x;
    const int cta = blockIdx.x;
    const int nt  = cta & 31;    // 64 gate-cols
    const int grp = cta >> 5;    // 0..7
    const int b0  = grp * 64;
    const int n0  = nt * 64;
    const int myq = nt >> 3;                       // my k-quarter (h cols nt*16 -> quarter)
    unsigned* sub = &g_sub[grp * 4 * 32];          // four counters, 128B apart
    unsigned* myctr = sub + myq * 32;

    const uint32_t sW32 = (uint32_t)__cvta_generic_to_shared(sW);
    const uint32_t sH32 = (uint32_t)__cvta_generic_to_shared(sH);

    // resident W slice: 64 rows x 512 halfs, 16 x 16B/thread
#pragma unroll
    for (int i = 0; i < 16; i++) {
        int id = i * 256 + tid; int row = id >> 6; int c8 = (id & 63) * 8;
        cpasync16(sW32 + (row * LDW + c8) * 2, g_W4h_h + (size_t)(n0 + row) * HH + c8);
    }
    cpasync_commit();

    const int lane = tid & 31, warp = tid >> 5;
    const int m0w = (warp >> 1) * 16;   // 4 m x 2 n warp grid
    const int n0w = (warp & 1) * 32;
    const int lg = lane >> 3, rl = lane & 7;
    const int gq = lane >> 2, t4 = lane & 3;
    const uint32_t aOff = ((m0w + (lg & 1) * 8 + rl) * LDH + (lg >> 1) * 8) * 2;
    const uint32_t aAddr[2] = { sH32 + aOff, sH32 + HCHUNK_B + aOff };
    uint32_t bAddr[2];
#pragma unroll
    for (int nj = 0; nj < 2; nj++) {
        int row = n0w + nj * 16 + (lg >> 1) * 8 + rl;
        bAddr[nj] = sW32 + (row * LDW + (lg & 1) * 8) * 2;
    }

    float C[4];

    // ---- prologue: step 0 (h = 0) ----
    {
        uint32_t xp[8];
        load_xp(xp, g_XP, b0, n0, m0w, n0w, gq, t4);
        float zacc[4][4] = {};
        do_stage(stg, zacc, xp, m0w, n0w, gq, t4);
        __syncthreads();
        do_gates(stg, tid, g_Hh[1], b0, nt, C, true);
        __threadfence();
        __syncthreads();
        if (tid == 0) ctr_arrive(myctr);
    }
    cpasync_waitg<0>();   // W slice resident

    // ---- main loop: pipelined quarter-waits + chunk loads ----
    for (int s = 1; s < SS; ++s) {
        uint32_t xp[8];
        load_xp(xp, g_XP + (size_t)s * BB * G4, b0, n0, m0w, n0w, gq, t4);

        const __half* hsrc = g_Hh[s & 1] + (size_t)b0 * HH;
        const unsigned tgt = (unsigned)s * 8;
        float acc[4][4] = {};

        ctr_wait(sub + 0 * 32, tgt);                 // k[0:128) producers done
        load_hchunk(sH32, hsrc, 0, tid);             cpasync_commit();
        ctr_wait(sub + 1 * 32, tgt);
        load_hchunk(sH32 + HCHUNK_B, hsrc, 128, tid); cpasync_commit();

        cpasync_waitg<1>(); __syncthreads();
        gemm_chunk(acc, aAddr[0], bAddr, 0);

        ctr_wait(sub + 2 * 32, tgt);                 // (also orders: all threads done reading buf0)
        load_hchunk(sH32, hsrc, 256, tid);           cpasync_commit();
        cpasync_waitg<1>(); __syncthreads();
        gemm_chunk(acc, aAddr[1], bAddr, 128);

        ctr_wait(sub + 3 * 32, tgt);
        load_hchunk(sH32 + HCHUNK_B, hsrc, 384, tid); cpasync_commit();
        cpasync_waitg<1>(); __syncthreads();
        gemm_chunk(acc, aAddr[0], bAddr, 256);

        cpasync_waitg<0>(); __syncthreads();
        gemm_chunk(acc, aAddr[1], bAddr, 384);

        // stage writes buf0; its last readers (chunk-256 gemm) all passed the sync above
        do_stage(stg, acc, xp, m0w, n0w, gq, t4);
        __syncthreads();
        do_gates(stg, tid, g_Hh[(s + 1) & 1], b0, nt, C, false);
        __threadfence();
        __syncthreads();
        if (tid == 0) ctr_arrive(myctr);
    }

    // ---- global barrier, then final projection (h(512) in g_Hh[0]) ----
    ctr_bar(&g_arrive, NCTA3);

    if (cta < 32) {
        const int pb0 = (cta >> 2) * 64;   // 8 row tiles
        const int pn0 = (cta & 3) * 64;    // 4 col tiles
#pragma unroll
        for (int i = 0; i < 16; i++) {
            int id = i * 256 + tid; int row = id >> 6; int c8 = (id & 63) * 8;
            *reinterpret_cast<uint4*>(sW + row * LDW + c8) =
                *reinterpret_cast<const uint4*>(g_Wp_h + (size_t)(pn0 + row) * HH + c8);
        }
        __syncthreads();

        float acc[4][4] = {};
        gemm_streamed(acc, g_Hh[0] + (size_t)pb0 * HH, sH32, aAddr, bAddr, tid);

#pragma unroll
        for (int ni = 0; ni < 4; ni++) {
            int r  = m0w + gq;
            int cl = n0w + ni * 8 + t4 * 2;
            float bv0 = bph[pn0 + cl], bv1 = bph[pn0 + cl + 1];
            out[(size_t)(pb0 + r) * OO + pn0 + cl]         = acc[ni][0] + bv0;
            out[(size_t)(pb0 + r) * OO + pn0 + cl + 1]     = acc[ni][1] + bv1;
            out[(size_t)(pb0 + r + 8) * OO + pn0 + cl]     = acc[ni][2] + bv0;
            out[(size_t)(pb0 + r + 8) * OO + pn0 + cl + 1] = acc[ni][3] + bv1;
        }
    }
}

// ---------------- launch ----------------
extern "C" void kernel_launch(void* const* d_in, const int* in_sizes, int n_in,
                              void* d_out, int out_size) {
    (void)in_sizes; (void)n_in; (void)out_size;
    const float* x   = (const float*)d_in[0];
    const float* Wgx = (const float*)d_in[1];
    const float* bgx = (const float*)d_in[2];
    const float* Wgh = (const float*)d_in[3];
    const float* bgh = (const float*)d_in[4];
    const float* Wix = (const float*)d_in[5];
    const float* bix = (const float*)d_in[6];
    const float* Wih = (const float*)d_in[7];
    const float* bih = (const float*)d_in[8];
    const float* Wfx = (const float*)d_in[9];
    const float* bfx = (const float*)d_in[10];
    const float* Wfh = (const float*)d_in[11];
    const float* bfh = (const float*)d_in[12];
    const float* Wox = (const float*)d_in[13];
    const float* box_ = (const float*)d_in[14];
    const float* Woh = (const float*)d_in[15];
    const float* boh = (const float*)d_in[16];
    const float* Wph = (const float*)d_in[17];
    const float* bph = (const float*)d_in[18];

    cudaFuncSetAttribute((const void*)xproj_kernel,
                         cudaFuncAttributeMaxDynamicSharedMemorySize, XPROJ_SMEM);
    cudaFuncSetAttribute((const void*)lstm_kernel,
                         cudaFuncAttributeMaxDynamicSharedMemorySize, LSTM_SMEM);

    pack_kernel<<<(G4 * HH) / PTHREADS, PTHREADS>>>(
        Wgx, Wgh, Wix, Wih, Wfx, Wfh, Wox, Woh,
        bgx, bgh, bix, bih, bfx, bfh, box_, boh, Wph);

    xconv_kernel<<<(BB * SS * II) / (PTHREADS * 8), PTHREADS>>>(x);

    dim3 g1(16, SS);   // 16 nt x 512 s; each CTA loops over 8 b-tiles
    xproj_kernel<<<g1, PTHREADS, XPROJ_SMEM>>>();

    lstm_kernel<<<NCTA3, LTHREADS, LSTM_SMEM>>>(bph, (float*)d_out);
}